// round 6
// baseline (speedup 1.0000x reference)
#include <cuda_runtime.h>
#include <cuda_bf16.h>
#include <cstdint>
#include <math.h>

#define NB   8
#define NC   256
#define NH   128
#define NW   128
#define NHW  (NH * NW)        // 16384

// ---------------------------------------------------------------------------
// Scratch (device globals: allocation-guard safe)
// ---------------------------------------------------------------------------
__device__ __nv_bfloat16 g_x_hi[(size_t)NB * NC * NHW];      // [b][c][n]
__device__ __nv_bfloat16 g_x_lo[(size_t)NB * NC * NHW];
__device__ __nv_bfloat16 g_qkv_hi[(size_t)NB * 3 * NC * NHW]; // [b][3C][n]
__device__ __nv_bfloat16 g_qkv_lo[(size_t)NB * 3 * NC * NHW];
__device__ __nv_bfloat16 g_att_hi[(size_t)NB * NC * NHW];
__device__ __nv_bfloat16 g_att_lo[(size_t)NB * NC * NHW];
__device__ __nv_bfloat16 g_w_hi[4 * NC * NC];                // wq,wk,wv,wo [o][c]
__device__ __nv_bfloat16 g_w_lo[4 * NC * NC];
__device__ float g_bias[4 * NC];

// ---------------------------------------------------------------------------
// PTX helpers (sm_80-baseline tensor core path; valid on compute_103)
// ---------------------------------------------------------------------------
__device__ __forceinline__ uint32_t smem_u32(const void* p) {
  uint32_t a;
  asm("{ .reg .u64 t; cvta.to.shared.u64 t, %1; cvt.u32.u64 %0, t; }"
      : "=r"(a) : "l"(p));
  return a;
}
__device__ __forceinline__ void cp_async16(uint32_t sdst, const void* gsrc) {
  asm volatile("cp.async.cg.shared.global [%0], [%1], 16;"
               :: "r"(sdst), "l"(gsrc));
}
#define CP_COMMIT() asm volatile("cp.async.commit_group;" ::: "memory")
#define CP_WAIT0()  asm volatile("cp.async.wait_group 0;" ::: "memory")
#define CP_WAIT1()  asm volatile("cp.async.wait_group 1;" ::: "memory")

__device__ __forceinline__ void ldsm_x4(uint32_t* r, uint32_t addr) {
  asm volatile("ldmatrix.sync.aligned.m8n8.x4.shared.b16 {%0,%1,%2,%3}, [%4];"
               : "=r"(r[0]), "=r"(r[1]), "=r"(r[2]), "=r"(r[3]) : "r"(addr));
}
__device__ __forceinline__ void ldsm_x4_t(uint32_t* r, uint32_t addr) {
  asm volatile("ldmatrix.sync.aligned.m8n8.x4.trans.shared.b16 {%0,%1,%2,%3}, [%4];"
               : "=r"(r[0]), "=r"(r[1]), "=r"(r[2]), "=r"(r[3]) : "r"(addr));
}
__device__ __forceinline__ void mma_bf16(float* d, const uint32_t* a,
                                         uint32_t b0, uint32_t b1) {
  asm volatile(
      "mma.sync.aligned.m16n8k16.row.col.f32.bf16.bf16.f32 "
      "{%0,%1,%2,%3}, {%4,%5,%6,%7}, {%8,%9}, {%0,%1,%2,%3};"
      : "+f"(d[0]), "+f"(d[1]), "+f"(d[2]), "+f"(d[3])
      : "r"(a[0]), "r"(a[1]), "r"(a[2]), "r"(a[3]), "r"(b0), "r"(b1));
}
__device__ __forceinline__ uint32_t pack_hi(float a, float b) {
  __nv_bfloat162 p = {__float2bfloat16(a), __float2bfloat16(b)};
  return *(uint32_t*)&p;
}
__device__ __forceinline__ uint32_t pack_lo(float a, float b) {
  __nv_bfloat16 ha = __float2bfloat16(a), hb = __float2bfloat16(b);
  __nv_bfloat162 p = {__float2bfloat16(a - __bfloat162float(ha)),
                      __float2bfloat16(b - __bfloat162float(hb))};
  return *(uint32_t*)&p;
}

// ---------------------------------------------------------------------------
// Elementwise bf16 split: fp32 -> hi + lo (same layout)
// ---------------------------------------------------------------------------
__global__ __launch_bounds__(256) void split_f32(
    const float* __restrict__ X, __nv_bfloat16* __restrict__ H,
    __nv_bfloat16* __restrict__ L) {
  int i = blockIdx.x * 256 + threadIdx.x;
  float4 v = ((const float4*)X)[i];
  ((uint2*)H)[i] = make_uint2(pack_hi(v.x, v.y), pack_hi(v.z, v.w));
  ((uint2*)L)[i] = make_uint2(pack_lo(v.x, v.y), pack_lo(v.z, v.w));
}

__global__ __launch_bounds__(256) void convert_w(
    const float* __restrict__ w0, const float* __restrict__ w1,
    const float* __restrict__ w2, const float* __restrict__ w3,
    const float* __restrict__ b0, const float* __restrict__ b1,
    const float* __restrict__ b2, const float* __restrict__ b3,
    __nv_bfloat16* __restrict__ H, __nv_bfloat16* __restrict__ L) {
  const float* ws[4] = {w0, w1, w2, w3};
  const float* bs[4] = {b0, b1, b2, b3};
  int m = blockIdx.y;
  int i = blockIdx.x * 256 + threadIdx.x;
  float v = ws[m][i];
  __nv_bfloat16 h = __float2bfloat16(v);
  H[m * NC * NC + i] = h;
  L[m * NC * NC + i] = __float2bfloat16(v - __bfloat162float(h));
  if (blockIdx.x == 0) g_bias[m * NC + threadIdx.x] = bs[m][threadIdx.x];
}

// ---------------------------------------------------------------------------
// mma.sync bf16-split GEMM (unchanged from round 5)
// ---------------------------------------------------------------------------
#define OFF_AH   0
#define OFF_AL   10240                 // 128*80
#define OFF_BH   20480
#define OFF_BL   29184                 // + 32*272
#define BUF_BYTES 37888
#define SMEM_GEMM (2 * BUF_BYTES)

__global__ __launch_bounds__(256, 2) void gemm_mma(
    const __nv_bfloat16* __restrict__ Xh, const __nv_bfloat16* __restrict__ Xl,
    const __nv_bfloat16* __restrict__ Wh, const __nv_bfloat16* __restrict__ Wl,
    const float* __restrict__ bias, float* __restrict__ Yf,
    __nv_bfloat16* __restrict__ Yh, __nv_bfloat16* __restrict__ Yl,
    int ocnt) {
  extern __shared__ __align__(16) char sm[];
  const uint32_t smb = smem_u32(sm);

  const int tid  = threadIdx.x;
  const int lane = tid & 31;
  const int wid  = tid >> 5;
  const int wm   = wid & 3;
  const int wn   = wid >> 2;
  const int b    = blockIdx.z;
  const int n0   = blockIdx.x * 128;
  const int o0   = blockIdx.y * 128;

  const __nv_bfloat16* Xbh = Xh + (size_t)b * NC * NHW + n0;
  const __nv_bfloat16* Xbl = Xl + (size_t)b * NC * NHW + n0;
  const __nv_bfloat16* Wbh = Wh + (size_t)o0 * NC;
  const __nv_bfloat16* Wbl = Wl + (size_t)o0 * NC;

  const int a_row0 = tid >> 2, a_seg = tid & 3;
  const int b_row0 = tid >> 4, b_seg = tid & 15;

  float acc[2][8][4];
#pragma unroll
  for (int mt = 0; mt < 2; mt++)
#pragma unroll
    for (int nt = 0; nt < 8; nt++)
#pragma unroll
      for (int e = 0; e < 4; e++) acc[mt][nt][e] = 0.f;

  const int lr = lane & 15, lc = lane >> 4;
  uint32_t a_base = (uint32_t)((wm * 32 + lr) * 80 + lc * 16);
  uint32_t b_base = (uint32_t)(lr * 272 + wn * 128 + lc * 16);

  auto stage = [&](int it) {
    const int c0 = it * 32;
    const uint32_t sb = smb + (it & 1) * BUF_BYTES;
#pragma unroll
    for (int r = 0; r < 2; r++) {
      int row = a_row0 + r * 64;
      uint32_t so = (uint32_t)(row * 80 + a_seg * 16);
      cp_async16(sb + OFF_AH + so, Wbh + (size_t)row * NC + c0 + a_seg * 8);
      cp_async16(sb + OFF_AL + so, Wbl + (size_t)row * NC + c0 + a_seg * 8);
    }
#pragma unroll
    for (int r = 0; r < 2; r++) {
      int row = b_row0 + r * 16;
      uint32_t so = (uint32_t)(row * 272 + b_seg * 16);
      cp_async16(sb + OFF_BH + so, Xbh + (size_t)(c0 + row) * NHW + b_seg * 8);
      cp_async16(sb + OFF_BL + so, Xbl + (size_t)(c0 + row) * NHW + b_seg * 8);
    }
    CP_COMMIT();
  };

  stage(0);

  for (int it = 0; it < 8; it++) {
    CP_WAIT0();
    __syncthreads();
    if (it + 1 < 8) stage(it + 1);

    const uint32_t sb = smb + (it & 1) * BUF_BYTES;
#pragma unroll
    for (int ks = 0; ks < 2; ks++) {
      uint32_t ah[2][4], al[2][4];
#pragma unroll
      for (int mt = 0; mt < 2; mt++) {
        uint32_t ao = sb + a_base + (uint32_t)(mt * 16 * 80 + ks * 32);
        ldsm_x4(ah[mt], ao + OFF_AH);
        ldsm_x4(al[mt], ao + OFF_AL);
      }
#pragma unroll
      for (int nt2 = 0; nt2 < 4; nt2++) {
        uint32_t bh[4], bl[4];
        uint32_t bo = sb + b_base + (uint32_t)(ks * 16 * 272 + nt2 * 32);
        ldsm_x4_t(bh, bo + OFF_BH);
        ldsm_x4_t(bl, bo + OFF_BL);
#pragma unroll
        for (int mt = 0; mt < 2; mt++) {
          mma_bf16(acc[mt][nt2 * 2],     ah[mt], bh[0], bh[1]);
          mma_bf16(acc[mt][nt2 * 2 + 1], ah[mt], bh[2], bh[3]);
          mma_bf16(acc[mt][nt2 * 2],     ah[mt], bl[0], bl[1]);
          mma_bf16(acc[mt][nt2 * 2 + 1], ah[mt], bl[2], bl[3]);
          mma_bf16(acc[mt][nt2 * 2],     al[mt], bh[0], bh[1]);
          mma_bf16(acc[mt][nt2 * 2 + 1], al[mt], bh[2], bh[3]);
        }
      }
    }
    __syncthreads();
  }

#pragma unroll
  for (int mt = 0; mt < 2; mt++) {
    int o = o0 + wm * 32 + mt * 16 + (lane >> 2);
    float bv0 = __ldg(bias + o);
    float bv1 = __ldg(bias + o + 8);
#pragma unroll
    for (int nt = 0; nt < 8; nt++) {
      int n = n0 + wn * 64 + nt * 8 + (lane & 3) * 2;
      float v00 = acc[mt][nt][0] + bv0, v01 = acc[mt][nt][1] + bv0;
      float v10 = acc[mt][nt][2] + bv1, v11 = acc[mt][nt][3] + bv1;
      size_t off0 = ((size_t)b * ocnt + o) * NHW + n;
      size_t off1 = ((size_t)b * ocnt + o + 8) * NHW + n;
      if (Yf) {
        *(float2*)(Yf + off0) = make_float2(v00, v01);
        *(float2*)(Yf + off1) = make_float2(v10, v11);
      } else {
        *(uint32_t*)(Yh + off0) = pack_hi(v00, v01);
        *(uint32_t*)(Yh + off1) = pack_hi(v10, v11);
        *(uint32_t*)(Yl + off0) = pack_lo(v00, v01);
        *(uint32_t*)(Yl + off1) = pack_lo(v10, v11);
      }
    }
  }
}

// ---------------------------------------------------------------------------
// Tensor-core attention v3: 512 threads / 16 warps per (b,c) slice.
// Warp w: rows rb*16..+15 (rb=w>>1), col-half ch*64 (ch=w&1).
// S in regs -> cross-warp softmax (2 warps/row, smem max/sum exchange) ->
// unnormalized P into smem (reusing Q region) -> PV -> normalize in epilogue.
// ---------------------------------------------------------------------------
#define AT_QH 0
#define AT_QL 34816
#define AT_KH 69632
#define AT_KL 104448
#define AT_VH 139264
#define AT_VL 174080
#define AT_RM 208896
#define AT_RS 209920
#define SMEM_ATTN3 210944

__global__ __launch_bounds__(512) void attn_mma(
    const __nv_bfloat16* __restrict__ QKVh,
    const __nv_bfloat16* __restrict__ QKVl,
    __nv_bfloat16* __restrict__ Oh, __nv_bfloat16* __restrict__ Ol) {
  extern __shared__ __align__(16) char sm[];
  const uint32_t smb = smem_u32(sm);
  float* redm = (float*)(sm + AT_RM);
  float* reds = (float*)(sm + AT_RS);

  const int tid  = threadIdx.x;
  const int lane = tid & 31;
  const int wid  = tid >> 5;
  const int rb   = wid >> 1;         // row block (16 rows)
  const int ch   = wid & 1;          // column half (64 cols)
  const int r0   = rb * 16;

  const int b = blockIdx.x >> 8;
  const int c = blockIdx.x & 255;
  const size_t qb = ((size_t)b * 3 * NC + c) * NHW;
  const size_t kb = qb + (size_t)NC * NHW;
  const size_t vb = qb + (size_t)2 * NC * NHW;

  // Stage Q,K (group 0) and V (group 1): 512 threads
  const int srow = tid >> 4, sseg = tid & 15;
#pragma unroll
  for (int r = 0; r < 4; r++) {
    int row = srow + r * 32;
    uint32_t so = (uint32_t)(row * 272 + sseg * 16);
    cp_async16(smb + AT_QH + so, QKVh + qb + row * 128 + sseg * 8);
    cp_async16(smb + AT_QL + so, QKVl + qb + row * 128 + sseg * 8);
    cp_async16(smb + AT_KH + so, QKVh + kb + row * 128 + sseg * 8);
    cp_async16(smb + AT_KL + so, QKVl + kb + row * 128 + sseg * 8);
  }
  CP_COMMIT();
#pragma unroll
  for (int r = 0; r < 4; r++) {
    int row = srow + r * 32;
    uint32_t so = (uint32_t)(row * 272 + sseg * 16);
    cp_async16(smb + AT_VH + so, QKVh + vb + row * 128 + sseg * 8);
    cp_async16(smb + AT_VL + so, QKVl + vb + row * 128 + sseg * 8);
  }
  CP_COMMIT();
  CP_WAIT1();          // Q,K ready
  __syncthreads();

  const int lr = lane & 15, lc = lane >> 4;
  const int g = lane >> 2, tig = lane & 3;

  float acc[8][4];
#pragma unroll
  for (int j = 0; j < 8; j++)
#pragma unroll
    for (int e = 0; e < 4; e++) acc[j][e] = 0.f;

  // S = Q K^T : warp covers rows r0..r0+15, cols ch*64..+63
#pragma unroll
  for (int ks = 0; ks < 8; ks++) {
    uint32_t qh[4], ql[4];
    uint32_t ao = smb + (uint32_t)((r0 + lr) * 272 + ks * 32 + lc * 16);
    ldsm_x4(qh, ao + AT_QH);
    ldsm_x4(ql, ao + AT_QL);
#pragma unroll
    for (int nt = 0; nt < 4; nt++) {
      uint32_t kh[4], kl[4];
      uint32_t bo = smb + (uint32_t)((ch * 64 + nt * 16 + lr) * 272 + ks * 32 + lc * 16);
      ldsm_x4(kh, bo + AT_KH);
      ldsm_x4(kl, bo + AT_KL);
      mma_bf16(acc[2 * nt],     qh, kh[0], kh[2]);
      mma_bf16(acc[2 * nt + 1], qh, kh[1], kh[3]);
      mma_bf16(acc[2 * nt],     qh, kl[0], kl[2]);
      mma_bf16(acc[2 * nt + 1], qh, kl[1], kl[3]);
      mma_bf16(acc[2 * nt],     ql, kh[0], kh[2]);
      mma_bf16(acc[2 * nt + 1], ql, kh[1], kh[3]);
    }
  }

  // Softmax across the two column-half warps.
  const float SCALE = 0.42044820762685725f;   // 32^(-1/4)
  float mA = -1e30f, mB = -1e30f;
#pragma unroll
  for (int j = 0; j < 8; j++) {
    acc[j][0] *= SCALE; acc[j][1] *= SCALE;
    acc[j][2] *= SCALE; acc[j][3] *= SCALE;
    mA = fmaxf(mA, fmaxf(acc[j][0], acc[j][1]));
    mB = fmaxf(mB, fmaxf(acc[j][2], acc[j][3]));
  }
  mA = fmaxf(mA, __shfl_xor_sync(0xffffffffu, mA, 1));
  mA = fmaxf(mA, __shfl_xor_sync(0xffffffffu, mA, 2));
  mB = fmaxf(mB, __shfl_xor_sync(0xffffffffu, mB, 1));
  mB = fmaxf(mB, __shfl_xor_sync(0xffffffffu, mB, 2));
  if (tig == 0) {
    redm[(r0 + g) * 2 + ch]     = mA;
    redm[(r0 + g + 8) * 2 + ch] = mB;
  }
  __syncthreads();     // also: all Q/K smem reads complete
  mA = fmaxf(redm[(r0 + g) * 2],     redm[(r0 + g) * 2 + 1]);
  mB = fmaxf(redm[(r0 + g + 8) * 2], redm[(r0 + g + 8) * 2 + 1]);

  float sA = 0.f, sB = 0.f;
#pragma unroll
  for (int j = 0; j < 8; j++) {
    acc[j][0] = __expf(acc[j][0] - mA);
    acc[j][1] = __expf(acc[j][1] - mA);
    acc[j][2] = __expf(acc[j][2] - mB);
    acc[j][3] = __expf(acc[j][3] - mB);
    sA += acc[j][0] + acc[j][1];
    sB += acc[j][2] + acc[j][3];
  }
  sA += __shfl_xor_sync(0xffffffffu, sA, 1);
  sA += __shfl_xor_sync(0xffffffffu, sA, 2);
  sB += __shfl_xor_sync(0xffffffffu, sB, 1);
  sB += __shfl_xor_sync(0xffffffffu, sB, 2);
  if (tig == 0) {
    reds[(r0 + g) * 2 + ch]     = sA;
    reds[(r0 + g + 8) * 2 + ch] = sB;
  }

  // Write unnormalized P hi/lo into the (dead) Q region.
#pragma unroll
  for (int j = 0; j < 8; j++) {
    uint32_t cA = (uint32_t)((r0 + g) * 272 + (ch * 64 + j * 8 + tig * 2) * 2);
    uint32_t cB = (uint32_t)((r0 + g + 8) * 272 + (ch * 64 + j * 8 + tig * 2) * 2);
    *(uint32_t*)(sm + AT_QH + cA) = pack_hi(acc[j][0], acc[j][1]);
    *(uint32_t*)(sm + AT_QH + cB) = pack_hi(acc[j][2], acc[j][3]);
    *(uint32_t*)(sm + AT_QL + cA) = pack_lo(acc[j][0], acc[j][1]);
    *(uint32_t*)(sm + AT_QL + cB) = pack_lo(acc[j][2], acc[j][3]);
  }
  CP_WAIT0();          // V ready
  __syncthreads();     // P + row sums visible

  const float rA = 1.0f / (reds[(r0 + g) * 2]     + reds[(r0 + g) * 2 + 1]);
  const float rB = 1.0f / (reds[(r0 + g + 8) * 2] + reds[(r0 + g + 8) * 2 + 1]);

  // O = P V : warp covers rows r0..r0+15, output cols ch*64..+63, full k=128
  float oac[8][4];
#pragma unroll
  for (int j = 0; j < 8; j++)
#pragma unroll
    for (int e = 0; e < 4; e++) oac[j][e] = 0.f;

#pragma unroll
  for (int ky = 0; ky < 8; ky++) {
    uint32_t ph[4], pl[4];
    uint32_t ao = smb + (uint32_t)((r0 + lr) * 272 + ky * 32 + lc * 16);
    ldsm_x4(ph, ao + AT_QH);
    ldsm_x4(pl, ao + AT_QL);
#pragma unroll
    for (int nt = 0; nt < 4; nt++) {
      uint32_t vh[4], vl[4];
      uint32_t bo = smb + (uint32_t)((ky * 16 + lr) * 272 + ch * 128 + nt * 32 + lc * 16);
      ldsm_x4_t(vh, bo + AT_VH);
      ldsm_x4_t(vl, bo + AT_VL);
      mma_bf16(oac[2 * nt],     ph, vh[0], vh[1]);
      mma_bf16(oac[2 * nt + 1], ph, vh[2], vh[3]);
      mma_bf16(oac[2 * nt],     ph, vl[0], vl[1]);
      mma_bf16(oac[2 * nt + 1], ph, vl[2], vl[3]);
      mma_bf16(oac[2 * nt],     pl, vh[0], vh[1]);
      mma_bf16(oac[2 * nt + 1], pl, vh[2], vh[3]);
    }
  }

  // Epilogue: normalize rows and write O hi/lo bf16 [b][c][row*128+col]
  const size_t ob = ((size_t)b * NC + c) * NHW;
  const int row0 = r0 + g, row1 = r0 + g + 8;
#pragma unroll
  for (int j = 0; j < 8; j++) {
    int col = ch * 64 + j * 8 + tig * 2;
    float v00 = oac[j][0] * rA, v01 = oac[j][1] * rA;
    float v10 = oac[j][2] * rB, v11 = oac[j][3] * rB;
    size_t o0 = ob + (size_t)row0 * 128 + col;
    size_t o1 = ob + (size_t)row1 * 128 + col;
    *(uint32_t*)(Oh + o0) = pack_hi(v00, v01);
    *(uint32_t*)(Oh + o1) = pack_hi(v10, v11);
    *(uint32_t*)(Ol + o0) = pack_lo(v00, v01);
    *(uint32_t*)(Ol + o1) = pack_lo(v10, v11);
  }
}

// ---------------------------------------------------------------------------
extern "C" void kernel_launch(void* const* d_in, const int* in_sizes, int n_in,
                              void* d_out, int out_size) {
  const float* x  = (const float*)d_in[0];
  const float* wq = (const float*)d_in[1];
  const float* bq = (const float*)d_in[2];
  const float* wk = (const float*)d_in[3];
  const float* bk = (const float*)d_in[4];
  const float* wv = (const float*)d_in[5];
  const float* bv = (const float*)d_in[6];
  const float* wo = (const float*)d_in[7];
  const float* bo = (const float*)d_in[8];

  __nv_bfloat16 *xh, *xl, *qkvh, *qkvl, *ath, *atl, *wh, *wl;
  float* bias;
  cudaGetSymbolAddress((void**)&xh,   g_x_hi);
  cudaGetSymbolAddress((void**)&xl,   g_x_lo);
  cudaGetSymbolAddress((void**)&qkvh, g_qkv_hi);
  cudaGetSymbolAddress((void**)&qkvl, g_qkv_lo);
  cudaGetSymbolAddress((void**)&ath,  g_att_hi);
  cudaGetSymbolAddress((void**)&atl,  g_att_lo);
  cudaGetSymbolAddress((void**)&wh,   g_w_hi);
  cudaGetSymbolAddress((void**)&wl,   g_w_lo);
  cudaGetSymbolAddress((void**)&bias, g_bias);

  cudaFuncSetAttribute(gemm_mma,
                       cudaFuncAttributeMaxDynamicSharedMemorySize, SMEM_GEMM);
  cudaFuncSetAttribute(attn_mma,
                       cudaFuncAttributeMaxDynamicSharedMemorySize, SMEM_ATTN3);

  // Convert inputs
  split_f32<<<NB * NC * NHW / 4 / 256, 256>>>(x, xh, xl);
  convert_w<<<dim3(NC * NC / 256, 4), 256>>>(wq, wk, wv, wo, bq, bk, bv, bo, wh, wl);

  // Fused QKV projection -> bf16 hi/lo
  gemm_mma<<<dim3(NHW / 128, 6, NB), 256, SMEM_GEMM>>>(
      xh, xl, wh, wl, bias, nullptr, qkvh, qkvl, 3 * NC);

  // Tensor-core attention -> bf16 hi/lo
  attn_mma<<<NB * NC, 512, SMEM_ATTN3>>>(qkvh, qkvl, ath, atl);

  // Output projection -> fp32 d_out
  gemm_mma<<<dim3(NHW / 128, 2, NB), 256, SMEM_GEMM>>>(
      ath, atl, wh + 3 * NC * NC, wl + 3 * NC * NC, bias + 3 * NC,
      (float*)d_out, nullptr, nullptr, NC);
}

// round 7
// speedup vs baseline: 1.0320x; 1.0320x over previous
#include <cuda_runtime.h>
#include <cuda_bf16.h>
#include <cstdint>
#include <math.h>

#define NB   8
#define NC   256
#define NH   128
#define NW   128
#define NHW  (NH * NW)        // 16384

// ---------------------------------------------------------------------------
// Scratch (device globals: allocation-guard safe)
// ---------------------------------------------------------------------------
__device__ __nv_bfloat16 g_x_hi[(size_t)NB * NC * NHW];      // [b][c][n]
__device__ __nv_bfloat16 g_x_lo[(size_t)NB * NC * NHW];
__device__ __nv_bfloat16 g_qkv_hi[(size_t)NB * 3 * NC * NHW]; // [b][3C][n]
__device__ __nv_bfloat16 g_qkv_lo[(size_t)NB * 3 * NC * NHW];
__device__ __nv_bfloat16 g_att_hi[(size_t)NB * NC * NHW];
__device__ __nv_bfloat16 g_att_lo[(size_t)NB * NC * NHW];
__device__ __nv_bfloat16 g_w_hi[4 * NC * NC];                // wq,wk,wv,wo [o][c]
__device__ __nv_bfloat16 g_w_lo[4 * NC * NC];
__device__ float g_bias[4 * NC];

// ---------------------------------------------------------------------------
// PTX helpers (sm_80-baseline tensor core path; valid on compute_103)
// ---------------------------------------------------------------------------
__device__ __forceinline__ uint32_t smem_u32(const void* p) {
  uint32_t a;
  asm("{ .reg .u64 t; cvta.to.shared.u64 t, %1; cvt.u32.u64 %0, t; }"
      : "=r"(a) : "l"(p));
  return a;
}
__device__ __forceinline__ void cp_async16(uint32_t sdst, const void* gsrc) {
  asm volatile("cp.async.cg.shared.global [%0], [%1], 16;"
               :: "r"(sdst), "l"(gsrc));
}
#define CP_COMMIT() asm volatile("cp.async.commit_group;" ::: "memory")
#define CP_WAIT0()  asm volatile("cp.async.wait_group 0;" ::: "memory")
#define CP_WAIT1()  asm volatile("cp.async.wait_group 1;" ::: "memory")

__device__ __forceinline__ void ldsm_x4(uint32_t* r, uint32_t addr) {
  asm volatile("ldmatrix.sync.aligned.m8n8.x4.shared.b16 {%0,%1,%2,%3}, [%4];"
               : "=r"(r[0]), "=r"(r[1]), "=r"(r[2]), "=r"(r[3]) : "r"(addr));
}
__device__ __forceinline__ void ldsm_x4_t(uint32_t* r, uint32_t addr) {
  asm volatile("ldmatrix.sync.aligned.m8n8.x4.trans.shared.b16 {%0,%1,%2,%3}, [%4];"
               : "=r"(r[0]), "=r"(r[1]), "=r"(r[2]), "=r"(r[3]) : "r"(addr));
}
__device__ __forceinline__ void mma_bf16(float* d, const uint32_t* a,
                                         uint32_t b0, uint32_t b1) {
  asm volatile(
      "mma.sync.aligned.m16n8k16.row.col.f32.bf16.bf16.f32 "
      "{%0,%1,%2,%3}, {%4,%5,%6,%7}, {%8,%9}, {%0,%1,%2,%3};"
      : "+f"(d[0]), "+f"(d[1]), "+f"(d[2]), "+f"(d[3])
      : "r"(a[0]), "r"(a[1]), "r"(a[2]), "r"(a[3]), "r"(b0), "r"(b1));
}
__device__ __forceinline__ uint32_t pack_hi(float a, float b) {
  __nv_bfloat162 p = {__float2bfloat16(a), __float2bfloat16(b)};
  return *(uint32_t*)&p;
}
__device__ __forceinline__ uint32_t pack_lo(float a, float b) {
  __nv_bfloat16 ha = __float2bfloat16(a), hb = __float2bfloat16(b);
  __nv_bfloat162 p = {__float2bfloat16(a - __bfloat162float(ha)),
                      __float2bfloat16(b - __bfloat162float(hb))};
  return *(uint32_t*)&p;
}

// ---------------------------------------------------------------------------
// Elementwise bf16 split: fp32 -> hi + lo (same layout)
// ---------------------------------------------------------------------------
__global__ __launch_bounds__(256) void split_f32(
    const float* __restrict__ X, __nv_bfloat16* __restrict__ H,
    __nv_bfloat16* __restrict__ L) {
  int i = blockIdx.x * 256 + threadIdx.x;
  float4 v = ((const float4*)X)[i];
  ((uint2*)H)[i] = make_uint2(pack_hi(v.x, v.y), pack_hi(v.z, v.w));
  ((uint2*)L)[i] = make_uint2(pack_lo(v.x, v.y), pack_lo(v.z, v.w));
}

__global__ __launch_bounds__(256) void convert_w(
    const float* __restrict__ w0, const float* __restrict__ w1,
    const float* __restrict__ w2, const float* __restrict__ w3,
    const float* __restrict__ b0, const float* __restrict__ b1,
    const float* __restrict__ b2, const float* __restrict__ b3,
    __nv_bfloat16* __restrict__ H, __nv_bfloat16* __restrict__ L) {
  const float* ws[4] = {w0, w1, w2, w3};
  const float* bs[4] = {b0, b1, b2, b3};
  int m = blockIdx.y;
  int i = blockIdx.x * 256 + threadIdx.x;
  float v = ws[m][i];
  __nv_bfloat16 h = __float2bfloat16(v);
  H[m * NC * NC + i] = h;
  L[m * NC * NC + i] = __float2bfloat16(v - __bfloat162float(h));
  if (blockIdx.x == 0) g_bias[m * NC + threadIdx.x] = bs[m][threadIdx.x];
}

// ---------------------------------------------------------------------------
// mma.sync bf16-split GEMM: D[o][n] = sum_c W[o][c] * X[c][n] + bias[o]
// CTA 128x128, K chunks 32, 3-stage cp.async ring (prefetch distance 2),
// 8 warps (4 o x 2 n).  launch_bounds(256,2): 2 CTAs/SM (227,328 B smem/SM).
// ---------------------------------------------------------------------------
#define OFF_AH   0
#define OFF_AL   10240                 // 128*80
#define OFF_BH   20480
#define OFF_BL   29184                 // + 32*272
#define BUF_BYTES 37888
#define SMEM_GEMM (3 * BUF_BYTES)      // 113664

__global__ __launch_bounds__(256, 2) void gemm_mma(
    const __nv_bfloat16* __restrict__ Xh, const __nv_bfloat16* __restrict__ Xl,
    const __nv_bfloat16* __restrict__ Wh, const __nv_bfloat16* __restrict__ Wl,
    const float* __restrict__ bias, float* __restrict__ Yf,
    __nv_bfloat16* __restrict__ Yh, __nv_bfloat16* __restrict__ Yl,
    int ocnt) {
  extern __shared__ __align__(16) char sm[];
  const uint32_t smb = smem_u32(sm);

  const int tid  = threadIdx.x;
  const int lane = tid & 31;
  const int wid  = tid >> 5;
  const int wm   = wid & 3;
  const int wn   = wid >> 2;
  const int b    = blockIdx.z;
  const int n0   = blockIdx.x * 128;
  const int o0   = blockIdx.y * 128;

  const __nv_bfloat16* Xbh = Xh + (size_t)b * NC * NHW + n0;
  const __nv_bfloat16* Xbl = Xl + (size_t)b * NC * NHW + n0;
  const __nv_bfloat16* Wbh = Wh + (size_t)o0 * NC;
  const __nv_bfloat16* Wbl = Wl + (size_t)o0 * NC;

  const int a_row0 = tid >> 2, a_seg = tid & 3;
  const int b_row0 = tid >> 4, b_seg = tid & 15;

  float acc[2][8][4];
#pragma unroll
  for (int mt = 0; mt < 2; mt++)
#pragma unroll
    for (int nt = 0; nt < 8; nt++)
#pragma unroll
      for (int e = 0; e < 4; e++) acc[mt][nt][e] = 0.f;

  const int lr = lane & 15, lc = lane >> 4;
  uint32_t a_base = (uint32_t)((wm * 32 + lr) * 80 + lc * 16);
  uint32_t b_base = (uint32_t)(lr * 272 + wn * 128 + lc * 16);

  auto stage = [&](int it, int slot) {
    const int c0 = it * 32;
    const uint32_t sb = smb + slot * BUF_BYTES;
#pragma unroll
    for (int r = 0; r < 2; r++) {
      int row = a_row0 + r * 64;
      uint32_t so = (uint32_t)(row * 80 + a_seg * 16);
      cp_async16(sb + OFF_AH + so, Wbh + (size_t)row * NC + c0 + a_seg * 8);
      cp_async16(sb + OFF_AL + so, Wbl + (size_t)row * NC + c0 + a_seg * 8);
    }
#pragma unroll
    for (int r = 0; r < 2; r++) {
      int row = b_row0 + r * 16;
      uint32_t so = (uint32_t)(row * 272 + b_seg * 16);
      cp_async16(sb + OFF_BH + so, Xbh + (size_t)(c0 + row) * NHW + b_seg * 8);
      cp_async16(sb + OFF_BL + so, Xbl + (size_t)(c0 + row) * NHW + b_seg * 8);
    }
    CP_COMMIT();
  };

  stage(0, 0);
  stage(1, 1);

  int slot = 0;        // slot of chunk `it`
  for (int it = 0; it < 8; it++) {
    if (it < 7) { CP_WAIT1(); } else { CP_WAIT0(); }
    __syncthreads();
    // Prefetch it+2 into the slot last read at iteration it-1 (safe: the
    // trailing __syncthreads of it-1 ordered all its reads before this point).
    int pslot = slot + 2 >= 3 ? slot - 1 : slot + 2;
    if (it + 2 < 8) stage(it + 2, pslot);

    const uint32_t sb = smb + slot * BUF_BYTES;
#pragma unroll
    for (int ks = 0; ks < 2; ks++) {
      uint32_t ah[2][4], al[2][4];
#pragma unroll
      for (int mt = 0; mt < 2; mt++) {
        uint32_t ao = sb + a_base + (uint32_t)(mt * 16 * 80 + ks * 32);
        ldsm_x4(ah[mt], ao + OFF_AH);
        ldsm_x4(al[mt], ao + OFF_AL);
      }
#pragma unroll
      for (int nt2 = 0; nt2 < 4; nt2++) {
        uint32_t bh[4], bl[4];
        uint32_t bo = sb + b_base + (uint32_t)(ks * 16 * 272 + nt2 * 32);
        ldsm_x4_t(bh, bo + OFF_BH);
        ldsm_x4_t(bl, bo + OFF_BL);
#pragma unroll
        for (int mt = 0; mt < 2; mt++) {
          mma_bf16(acc[mt][nt2 * 2],     ah[mt], bh[0], bh[1]);
          mma_bf16(acc[mt][nt2 * 2 + 1], ah[mt], bh[2], bh[3]);
          mma_bf16(acc[mt][nt2 * 2],     ah[mt], bl[0], bl[1]);
          mma_bf16(acc[mt][nt2 * 2 + 1], ah[mt], bl[2], bl[3]);
          mma_bf16(acc[mt][nt2 * 2],     al[mt], bh[0], bh[1]);
          mma_bf16(acc[mt][nt2 * 2 + 1], al[mt], bh[2], bh[3]);
        }
      }
    }
    __syncthreads();
    slot = slot + 1 >= 3 ? 0 : slot + 1;
  }

#pragma unroll
  for (int mt = 0; mt < 2; mt++) {
    int o = o0 + wm * 32 + mt * 16 + (lane >> 2);
    float bv0 = __ldg(bias + o);
    float bv1 = __ldg(bias + o + 8);
#pragma unroll
    for (int nt = 0; nt < 8; nt++) {
      int n = n0 + wn * 64 + nt * 8 + (lane & 3) * 2;
      float v00 = acc[mt][nt][0] + bv0, v01 = acc[mt][nt][1] + bv0;
      float v10 = acc[mt][nt][2] + bv1, v11 = acc[mt][nt][3] + bv1;
      size_t off0 = ((size_t)b * ocnt + o) * NHW + n;
      size_t off1 = ((size_t)b * ocnt + o + 8) * NHW + n;
      if (Yf) {
        *(float2*)(Yf + off0) = make_float2(v00, v01);
        *(float2*)(Yf + off1) = make_float2(v10, v11);
      } else {
        *(uint32_t*)(Yh + off0) = pack_hi(v00, v01);
        *(uint32_t*)(Yh + off1) = pack_hi(v10, v11);
        *(uint32_t*)(Yl + off0) = pack_lo(v00, v01);
        *(uint32_t*)(Yl + off1) = pack_lo(v10, v11);
      }
    }
  }
}

// ---------------------------------------------------------------------------
// Tensor-core attention (round-5 version — best measured): one CTA per (b,c),
// 256 threads, each warp owns 16 full rows; S and P fully register-resident.
// ---------------------------------------------------------------------------
#define AT_QH 0
#define AT_QL 34816
#define AT_KH 69632
#define AT_KL 104448
#define AT_VH 139264
#define AT_VL 174080
#define SMEM_ATTN2 208896

__global__ __launch_bounds__(256) void attn_mma(
    const __nv_bfloat16* __restrict__ QKVh,
    const __nv_bfloat16* __restrict__ QKVl,
    __nv_bfloat16* __restrict__ Oh, __nv_bfloat16* __restrict__ Ol) {
  extern __shared__ __align__(16) char sm[];
  const uint32_t smb = smem_u32(sm);

  const int tid  = threadIdx.x;
  const int lane = tid & 31;
  const int wid  = tid >> 5;

  const int b = blockIdx.x >> 8;
  const int c = blockIdx.x & 255;
  const size_t qb = ((size_t)b * 3 * NC + c) * NHW;
  const size_t kb = qb + (size_t)NC * NHW;
  const size_t vb = qb + (size_t)2 * NC * NHW;

  // Stage Q,K (group 0) and V (group 1)
  const int srow = tid >> 4, sseg = tid & 15;
#pragma unroll
  for (int r = 0; r < 8; r++) {
    int row = srow + r * 16;
    uint32_t so = (uint32_t)(row * 272 + sseg * 16);
    cp_async16(smb + AT_QH + so, QKVh + qb + row * 128 + sseg * 8);
    cp_async16(smb + AT_QL + so, QKVl + qb + row * 128 + sseg * 8);
    cp_async16(smb + AT_KH + so, QKVh + kb + row * 128 + sseg * 8);
    cp_async16(smb + AT_KL + so, QKVl + kb + row * 128 + sseg * 8);
  }
  CP_COMMIT();
#pragma unroll
  for (int r = 0; r < 8; r++) {
    int row = srow + r * 16;
    uint32_t so = (uint32_t)(row * 272 + sseg * 16);
    cp_async16(smb + AT_VH + so, QKVh + vb + row * 128 + sseg * 8);
    cp_async16(smb + AT_VL + so, QKVl + vb + row * 128 + sseg * 8);
  }
  CP_COMMIT();
  CP_WAIT1();          // Q,K ready
  __syncthreads();

  const int lr = lane & 15, lc = lane >> 4;
  const int r0 = wid * 16;

  float acc[16][4];
#pragma unroll
  for (int j = 0; j < 16; j++)
#pragma unroll
    for (int e = 0; e < 4; e++) acc[j][e] = 0.f;

  // S = Q K^T : warp covers rows r0..r0+15, all 128 cols
#pragma unroll
  for (int ks = 0; ks < 8; ks++) {
    uint32_t qh[4], ql[4];
    uint32_t ao = smb + (uint32_t)((r0 + lr) * 272 + ks * 32 + lc * 16);
    ldsm_x4(qh, ao + AT_QH);
    ldsm_x4(ql, ao + AT_QL);
#pragma unroll
    for (int nt = 0; nt < 8; nt++) {
      uint32_t kh[4], kl[4];
      uint32_t bo = smb + (uint32_t)((nt * 16 + lr) * 272 + ks * 32 + lc * 16);
      ldsm_x4(kh, bo + AT_KH);
      ldsm_x4(kl, bo + AT_KL);
      mma_bf16(acc[2 * nt],     qh, kh[0], kh[2]);
      mma_bf16(acc[2 * nt + 1], qh, kh[1], kh[3]);
      mma_bf16(acc[2 * nt],     qh, kl[0], kl[2]);
      mma_bf16(acc[2 * nt + 1], qh, kl[1], kl[3]);
      mma_bf16(acc[2 * nt],     ql, kh[0], kh[2]);
      mma_bf16(acc[2 * nt + 1], ql, kh[1], kh[3]);
    }
  }

  // Register softmax: thread owns 2 rows (g, g+8), 32 values each,
  // spread over the 4 lanes with the same lane>>2 -> shfl_xor 1,2.
  const float SCALE = 0.42044820762685725f;   // 32^(-1/4)
  float mA = -1e30f, mB = -1e30f;
#pragma unroll
  for (int j = 0; j < 16; j++) {
    acc[j][0] *= SCALE; acc[j][1] *= SCALE;
    acc[j][2] *= SCALE; acc[j][3] *= SCALE;
    mA = fmaxf(mA, fmaxf(acc[j][0], acc[j][1]));
    mB = fmaxf(mB, fmaxf(acc[j][2], acc[j][3]));
  }
  mA = fmaxf(mA, __shfl_xor_sync(0xffffffffu, mA, 1));
  mA = fmaxf(mA, __shfl_xor_sync(0xffffffffu, mA, 2));
  mB = fmaxf(mB, __shfl_xor_sync(0xffffffffu, mB, 1));
  mB = fmaxf(mB, __shfl_xor_sync(0xffffffffu, mB, 2));
  float sA = 0.f, sB = 0.f;
#pragma unroll
  for (int j = 0; j < 16; j++) {
    acc[j][0] = __expf(acc[j][0] - mA);
    acc[j][1] = __expf(acc[j][1] - mA);
    acc[j][2] = __expf(acc[j][2] - mB);
    acc[j][3] = __expf(acc[j][3] - mB);
    sA += acc[j][0] + acc[j][1];
    sB += acc[j][2] + acc[j][3];
  }
  sA += __shfl_xor_sync(0xffffffffu, sA, 1);
  sA += __shfl_xor_sync(0xffffffffu, sA, 2);
  sB += __shfl_xor_sync(0xffffffffu, sB, 1);
  sB += __shfl_xor_sync(0xffffffffu, sB, 2);
  const float rA = 1.0f / sA, rB = 1.0f / sB;

  // Convert P accumulator fragments directly to A-operand fragments (hi/lo).
  uint32_t ph[8][4], pl[8][4];
#pragma unroll
  for (int ky = 0; ky < 8; ky++) {
    const int j0 = 2 * ky, j1 = 2 * ky + 1;
    float p00 = acc[j0][0] * rA, p01 = acc[j0][1] * rA;
    float p02 = acc[j0][2] * rB, p03 = acc[j0][3] * rB;
    float p10 = acc[j1][0] * rA, p11 = acc[j1][1] * rA;
    float p12 = acc[j1][2] * rB, p13 = acc[j1][3] * rB;
    ph[ky][0] = pack_hi(p00, p01); ph[ky][1] = pack_hi(p02, p03);
    ph[ky][2] = pack_hi(p10, p11); ph[ky][3] = pack_hi(p12, p13);
    pl[ky][0] = pack_lo(p00, p01); pl[ky][1] = pack_lo(p02, p03);
    pl[ky][2] = pack_lo(p10, p11); pl[ky][3] = pack_lo(p12, p13);
  }

  CP_WAIT0();          // V ready
  __syncthreads();

  // O = P V
  float oac[16][4];
#pragma unroll
  for (int j = 0; j < 16; j++)
#pragma unroll
    for (int e = 0; e < 4; e++) oac[j][e] = 0.f;

#pragma unroll
  for (int ky = 0; ky < 8; ky++) {
#pragma unroll
    for (int nt = 0; nt < 8; nt++) {
      uint32_t vh[4], vl[4];
      uint32_t bo = smb + (uint32_t)((ky * 16 + lr) * 272 + nt * 32 + lc * 16);
      ldsm_x4_t(vh, bo + AT_VH);
      ldsm_x4_t(vl, bo + AT_VL);
      mma_bf16(oac[2 * nt],     ph[ky], vh[0], vh[1]);
      mma_bf16(oac[2 * nt + 1], ph[ky], vh[2], vh[3]);
      mma_bf16(oac[2 * nt],     ph[ky], vl[0], vl[1]);
      mma_bf16(oac[2 * nt + 1], ph[ky], vl[2], vl[3]);
      mma_bf16(oac[2 * nt],     pl[ky], vh[0], vh[1]);
      mma_bf16(oac[2 * nt + 1], pl[ky], vh[2], vh[3]);
    }
  }

  // Epilogue: write O hi/lo bf16 [b][c][row*128+col]
  const size_t ob = ((size_t)b * NC + c) * NHW;
  const int g = lane >> 2, tig = lane & 3;
  const int row0 = r0 + g, row1 = r0 + g + 8;
#pragma unroll
  for (int j = 0; j < 16; j++) {
    int col = j * 8 + tig * 2;
    size_t o0 = ob + (size_t)row0 * 128 + col;
    size_t o1 = ob + (size_t)row1 * 128 + col;
    *(uint32_t*)(Oh + o0) = pack_hi(oac[j][0], oac[j][1]);
    *(uint32_t*)(Oh + o1) = pack_hi(oac[j][2], oac[j][3]);
    *(uint32_t*)(Ol + o0) = pack_lo(oac[j][0], oac[j][1]);
    *(uint32_t*)(Ol + o1) = pack_lo(oac[j][2], oac[j][3]);
  }
}

// ---------------------------------------------------------------------------
extern "C" void kernel_launch(void* const* d_in, const int* in_sizes, int n_in,
                              void* d_out, int out_size) {
  const float* x  = (const float*)d_in[0];
  const float* wq = (const float*)d_in[1];
  const float* bq = (const float*)d_in[2];
  const float* wk = (const float*)d_in[3];
  const float* bk = (const float*)d_in[4];
  const float* wv = (const float*)d_in[5];
  const float* bv = (const float*)d_in[6];
  const float* wo = (const float*)d_in[7];
  const float* bo = (const float*)d_in[8];

  __nv_bfloat16 *xh, *xl, *qkvh, *qkvl, *ath, *atl, *wh, *wl;
  float* bias;
  cudaGetSymbolAddress((void**)&xh,   g_x_hi);
  cudaGetSymbolAddress((void**)&xl,   g_x_lo);
  cudaGetSymbolAddress((void**)&qkvh, g_qkv_hi);
  cudaGetSymbolAddress((void**)&qkvl, g_qkv_lo);
  cudaGetSymbolAddress((void**)&ath,  g_att_hi);
  cudaGetSymbolAddress((void**)&atl,  g_att_lo);
  cudaGetSymbolAddress((void**)&wh,   g_w_hi);
  cudaGetSymbolAddress((void**)&wl,   g_w_lo);
  cudaGetSymbolAddress((void**)&bias, g_bias);

  cudaFuncSetAttribute(gemm_mma,
                       cudaFuncAttributeMaxDynamicSharedMemorySize, SMEM_GEMM);
  cudaFuncSetAttribute(attn_mma,
                       cudaFuncAttributeMaxDynamicSharedMemorySize, SMEM_ATTN2);

  // Convert inputs
  split_f32<<<NB * NC * NHW / 4 / 256, 256>>>(x, xh, xl);
  convert_w<<<dim3(NC * NC / 256, 4), 256>>>(wq, wk, wv, wo, bq, bk, bv, bo, wh, wl);

  // Fused QKV projection -> bf16 hi/lo
  gemm_mma<<<dim3(NHW / 128, 6, NB), 256, SMEM_GEMM>>>(
      xh, xl, wh, wl, bias, nullptr, qkvh, qkvl, 3 * NC);

  // Tensor-core attention -> bf16 hi/lo
  attn_mma<<<NB * NC, 256, SMEM_ATTN2>>>(qkvh, qkvl, ath, atl);

  // Output projection -> fp32 d_out
  gemm_mma<<<dim3(NHW / 128, 2, NB), 256, SMEM_GEMM>>>(
      ath, atl, wh + 3 * NC * NC, wl + 3 * NC * NC, bias + 3 * NC,
      (float*)d_out, nullptr, nullptr, NC);
}